// round 1
// baseline (speedup 1.0000x reference)
#include <cuda_runtime.h>

// Problem shape (fixed by reference): image (16, 3, 1024, 1024) fp32, rgb2yuv (3,3) fp32.
#define BATCH 16
#define HW (1 << 20)          // 1024*1024 pixels per batch per channel
#define CB 4096               // coarse histogram bins (12 bit)
#define FB 4096               // fine histogram bins (12 bit) -> 24-bit total quantization
#define CHUNKS 64             // CTAs per batch for the big passes
#define NT 256                // threads per CTA
#define F4_PER_CTA ((HW / 4) / CHUNKS)   // 4096 float4 per CTA

// Order-statistic ranks for jnp.percentile(q, method='linear'), n = 1048576:
//   blk: idx = 0.01*(n-1) = 10485.75   -> k=10485, frac=0.75
//   wht: idx = 0.99*(n-1) = 1038089.25 -> k=1038089, frac=0.25
#define RANK0 10485u
#define RANK1 10486u
#define RANK2 1038089u
#define RANK3 1038090u

// ---------------- device scratch (allowed: __device__ globals) ----------------
__device__ float    g_Y[(size_t)BATCH * HW];      // 64 MB luma scratch
__device__ unsigned g_hist[BATCH][CB];            // coarse hists
__device__ unsigned g_hist2[BATCH][4][FB];        // fine hists (one per target rank)
__device__ int      g_tbin[BATCH][4];             // target coarse bin per rank
__device__ int      g_trank[BATCH][4];            // rank within that coarse bin
__device__ float    g_blk[BATCH];
__device__ float    g_mult[BATCH];

// ---------------- kernel 0: zero the histograms (graph replays need this) ----
__global__ void __launch_bounds__(NT) k_zero() {
    unsigned idx = blockIdx.x * NT + threadIdx.x;
    unsigned stride = gridDim.x * NT;
    unsigned* h1 = &g_hist[0][0];
    unsigned* h2 = &g_hist2[0][0][0];
    for (unsigned i = idx; i < BATCH * CB; i += stride) h1[i] = 0u;
    for (unsigned i = idx; i < BATCH * 4 * FB; i += stride) h2[i] = 0u;
}

// ---------------- kernel 1: Y = rgb2yuv[0]·rgb, store Y, coarse histogram ----
__global__ void __launch_bounds__(NT) k_yhist(const float* __restrict__ img,
                                              const float* __restrict__ mat) {
    __shared__ unsigned sh[CB];
    const int b = blockIdx.y;
    const int chunk = blockIdx.x;

    #pragma unroll
    for (int j = threadIdx.x; j < CB; j += NT) sh[j] = 0u;
    __syncthreads();

    const float c0 = mat[0], c1 = mat[1], c2 = mat[2];
    const size_t base = (size_t)b * 3 * HW;
    const float4* __restrict__ R  = (const float4*)(img + base);
    const float4* __restrict__ G  = (const float4*)(img + base + HW);
    const float4* __restrict__ Bc = (const float4*)(img + base + 2 * (size_t)HW);
    float4* __restrict__ Y = (float4*)(g_Y + (size_t)b * HW);

    const int off = chunk * F4_PER_CTA;
    #pragma unroll 4
    for (int i = threadIdx.x; i < F4_PER_CTA; i += NT) {
        float4 r = R[off + i];
        float4 g = G[off + i];
        float4 v = Bc[off + i];
        float4 y;
        y.x = c0 * r.x + c1 * g.x + c2 * v.x;
        y.y = c0 * r.y + c1 * g.y + c2 * v.y;
        y.z = c0 * r.z + c1 * g.z + c2 * v.z;
        y.w = c0 * r.w + c1 * g.w + c2 * v.w;
        Y[off + i] = y;
        int b0 = min((int)(y.x * 4096.0f), CB - 1);
        int b1 = min((int)(y.y * 4096.0f), CB - 1);
        int b2 = min((int)(y.z * 4096.0f), CB - 1);
        int b3 = min((int)(y.w * 4096.0f), CB - 1);
        atomicAdd(&sh[b0], 1u);
        atomicAdd(&sh[b1], 1u);
        atomicAdd(&sh[b2], 1u);
        atomicAdd(&sh[b3], 1u);
    }
    __syncthreads();

    for (int j = threadIdx.x; j < CB; j += NT) {
        unsigned v = sh[j];
        if (v) atomicAdd(&g_hist[b][j], v);
    }
}

// ---------------- kernel 2: find coarse bin + intra-bin rank for 4 targets --
__global__ void __launch_bounds__(NT) k_coarse_select() {
    __shared__ unsigned psum[NT];
    const int b = blockIdx.x;
    const unsigned* __restrict__ h = g_hist[b];
    const int W = CB / NT;                  // 16 bins per thread
    const int base = threadIdx.x * W;

    unsigned local = 0;
    #pragma unroll
    for (int j = 0; j < W; j++) local += h[base + j];
    psum[threadIdx.x] = local;
    __syncthreads();
    if (threadIdx.x == 0) {
        unsigned cum = 0;
        for (int i = 0; i < NT; i++) { unsigned c = psum[i]; psum[i] = cum; cum += c; }
    }
    __syncthreads();
    const unsigned pre = psum[threadIdx.x];

    const unsigned ranks[4] = {RANK0, RANK1, RANK2, RANK3};
    #pragma unroll
    for (int t = 0; t < 4; t++) {
        unsigned r = ranks[t];
        if (r >= pre && r < pre + local) {
            unsigned cum = pre;
            for (int j = 0; j < W; j++) {
                unsigned c = h[base + j];
                if (r < cum + c) {
                    g_tbin[b][t] = base + j;
                    g_trank[b][t] = (int)(r - cum);
                    break;
                }
                cum += c;
            }
        }
    }
}

// ---------------- kernel 3: fine histogram over Y for target coarse bins -----
__global__ void __launch_bounds__(NT) k_fine(int /*dummy*/) {
    const int b = blockIdx.y;
    const int chunk = blockIdx.x;
    const int tb0 = g_tbin[b][0];
    const int tb1 = g_tbin[b][1];
    const int tb2 = g_tbin[b][2];
    const int tb3 = g_tbin[b][3];

    const float4* __restrict__ Y = (const float4*)(g_Y + (size_t)b * HW);
    const int off = chunk * F4_PER_CTA;

    #pragma unroll 4
    for (int i = threadIdx.x; i < F4_PER_CTA; i += NT) {
        float4 y = Y[off + i];
        float ys[4] = {y.x, y.y, y.z, y.w};
        #pragma unroll
        for (int k = 0; k < 4; k++) {
            float s = ys[k] * 4096.0f;            // exact (power-of-2 scale)
            int cb = min((int)s, CB - 1);
            if (cb == tb0 || cb == tb1 || cb == tb2 || cb == tb3) {
                int fb = min((int)((s - (float)cb) * 4096.0f), FB - 1);
                if (cb == tb0) atomicAdd(&g_hist2[b][0][fb], 1u);
                if (cb == tb1) atomicAdd(&g_hist2[b][1][fb], 1u);
                if (cb == tb2) atomicAdd(&g_hist2[b][2][fb], 1u);
                if (cb == tb3) atomicAdd(&g_hist2[b][3][fb], 1u);
            }
        }
    }
}

// ---------------- kernel 4: resolve fine bins, compute blkpt & mult ----------
__global__ void __launch_bounds__(NT) k_select() {
    __shared__ unsigned psum[NT];
    __shared__ float vals[4];
    const int b = blockIdx.x;
    const int W = FB / NT;
    const int base = threadIdx.x * W;

    for (int t = 0; t < 4; t++) {
        const unsigned* __restrict__ h = g_hist2[b][t];
        const int tb = g_tbin[b][t];
        const unsigned tr = (unsigned)g_trank[b][t];

        unsigned local = 0;
        #pragma unroll
        for (int j = 0; j < W; j++) local += h[base + j];
        psum[threadIdx.x] = local;
        __syncthreads();
        if (threadIdx.x == 0) {
            unsigned cum = 0;
            for (int i = 0; i < NT; i++) { unsigned c = psum[i]; psum[i] = cum; cum += c; }
        }
        __syncthreads();
        unsigned pre = psum[threadIdx.x];
        if (tr >= pre && tr < pre + local) {
            unsigned cum = pre;
            for (int j = 0; j < W; j++) {
                unsigned c = h[base + j];
                if (tr < cum + c) {
                    vals[t] = ((float)tb + ((float)(base + j) + 0.5f) * (1.0f / 4096.0f))
                              * (1.0f / 4096.0f);
                    break;
                }
                cum += c;
            }
        }
        __syncthreads();
    }

    if (threadIdx.x == 0) {
        float blk = 0.25f * vals[0] + 0.75f * vals[1];
        float wht = 0.75f * vals[2] + 0.25f * vals[3];
        float m = fminf(1.0f / (wht - blk), 1.5f);
        g_blk[b] = blk;
        g_mult[b] = m;
    }
}

// ---------------- kernel 5: out = clip((img - blk)*mult, 0, 1) ---------------
__global__ void __launch_bounds__(NT) k_apply(const float* __restrict__ img,
                                              float* __restrict__ out) {
    const int b = blockIdx.y;
    const float blk = g_blk[b];
    const float m = g_mult[b];
    const size_t base = (size_t)b * 3 * (HW / 4);
    const float4* __restrict__ in4 = (const float4*)img + base;
    float4* __restrict__ o4 = (float4*)out + base;
    const int n = 3 * (HW / 4);                 // 786432 float4 per batch
    const int stride = gridDim.x * NT;

    for (int i = blockIdx.x * NT + threadIdx.x; i < n; i += stride) {
        float4 v = in4[i];
        float4 r;
        r.x = fminf(fmaxf((v.x - blk) * m, 0.0f), 1.0f);
        r.y = fminf(fmaxf((v.y - blk) * m, 0.0f), 1.0f);
        r.z = fminf(fmaxf((v.z - blk) * m, 0.0f), 1.0f);
        r.w = fminf(fmaxf((v.w - blk) * m, 0.0f), 1.0f);
        o4[i] = r;
    }
}

// ---------------- launch ------------------------------------------------------
extern "C" void kernel_launch(void* const* d_in, const int* in_sizes, int n_in,
                              void* d_out, int out_size) {
    const float* img = (const float*)d_in[0];
    const float* mat = (const float*)d_in[1];
    float* out = (float*)d_out;

    k_zero<<<160, NT>>>();

    dim3 gBig(CHUNKS, BATCH);
    k_yhist<<<gBig, NT>>>(img, mat);
    k_coarse_select<<<BATCH, NT>>>();
    k_fine<<<gBig, NT>>>(0);
    k_select<<<BATCH, NT>>>();

    dim3 gApply(384, BATCH);
    k_apply<<<gApply, NT>>>(img, out);
}

// round 2
// speedup vs baseline: 1.1796x; 1.1796x over previous
#include <cuda_runtime.h>

#define BATCH 16
#define HW (1 << 20)
#define CB 4096                 // coarse bins (q >> 4)
#define FBITS 4                 // fine bins = 16 (q & 15)
#define CHUNKS 64
#define NT 256
#define F4_PER_CTA ((HW / 4) / CHUNKS)     // 4096 float4 per CTA in yhist

// percentile ranks, n = 1048576 (linear interp):
// blk: 0.25*v[10485] + 0.75*v[10486] ; wht: 0.75*v[1038089] + 0.25*v[1038090]
#define RANK0 10485u
#define RANK1 10486u
#define RANK2 1038089u
#define RANK3 1038090u

// ---------------- device scratch ----------------
__device__ unsigned short g_Y16[(size_t)BATCH * HW];   // 32 MB quantized luma
__device__ unsigned g_hist[BATCH][CB];                 // coarse hists
__device__ unsigned g_hist2[BATCH][4][16];             // fine hists (tiny)
__device__ int      g_tbin[BATCH][4];
__device__ int      g_trank[BATCH][4];

// ------------- kernel 1: Y16 + coarse hist (also zeroes g_hist2 for this replay) -------------
__global__ void __launch_bounds__(NT) k_yhist(const float* __restrict__ img,
                                              const float* __restrict__ mat) {
    __shared__ unsigned sh[CB];
    const int b = blockIdx.y;
    const int chunk = blockIdx.x;

    if (blockIdx.x == 0 && threadIdx.x < 64)
        ((unsigned*)g_hist2[b])[threadIdx.x] = 0u;

    for (int j = threadIdx.x; j < CB; j += NT) sh[j] = 0u;
    __syncthreads();

    const float c0 = mat[0], c1 = mat[1], c2 = mat[2];
    const size_t base = (size_t)b * 3 * HW;
    const float4* __restrict__ R  = (const float4*)(img + base);
    const float4* __restrict__ G  = (const float4*)(img + base + HW);
    const float4* __restrict__ Bc = (const float4*)(img + base + 2 * (size_t)HW);
    uint2* __restrict__ Y = (uint2*)(g_Y16 + (size_t)b * HW);

    const int off = chunk * F4_PER_CTA;
    #pragma unroll 4
    for (int i = threadIdx.x; i < F4_PER_CTA; i += NT) {
        float4 r = R[off + i];
        float4 g = G[off + i];
        float4 v = Bc[off + i];
        float y0 = c0 * r.x + c1 * g.x + c2 * v.x;
        float y1 = c0 * r.y + c1 * g.y + c2 * v.y;
        float y2 = c0 * r.z + c1 * g.z + c2 * v.z;
        float y3 = c0 * r.w + c1 * g.w + c2 * v.w;
        unsigned q0 = min((unsigned)(y0 * 65536.0f), 65535u);
        unsigned q1 = min((unsigned)(y1 * 65536.0f), 65535u);
        unsigned q2 = min((unsigned)(y2 * 65536.0f), 65535u);
        unsigned q3 = min((unsigned)(y3 * 65536.0f), 65535u);
        uint2 st;
        st.x = q0 | (q1 << 16);
        st.y = q2 | (q3 << 16);
        Y[off + i] = st;
        atomicAdd(&sh[q0 >> FBITS], 1u);
        atomicAdd(&sh[q1 >> FBITS], 1u);
        atomicAdd(&sh[q2 >> FBITS], 1u);
        atomicAdd(&sh[q3 >> FBITS], 1u);
    }
    __syncthreads();

    for (int j = threadIdx.x; j < CB; j += NT) {
        unsigned v = sh[j];
        if (v) atomicAdd(&g_hist[b][j], v);
    }
}

// ------------- kernel 2: coarse bin + intra-bin rank for the 4 targets -------------
__global__ void __launch_bounds__(NT) k_coarse_select() {
    __shared__ unsigned psum[NT];
    const int b = blockIdx.x;
    const unsigned* __restrict__ h = g_hist[b];
    const int W = CB / NT;                 // 16
    const int base = threadIdx.x * W;

    unsigned local = 0;
    #pragma unroll
    for (int j = 0; j < W; j++) local += h[base + j];
    psum[threadIdx.x] = local;
    __syncthreads();
    if (threadIdx.x == 0) {
        unsigned cum = 0;
        for (int i = 0; i < NT; i++) { unsigned c = psum[i]; psum[i] = cum; cum += c; }
    }
    __syncthreads();
    const unsigned pre = psum[threadIdx.x];

    const unsigned ranks[4] = {RANK0, RANK1, RANK2, RANK3};
    #pragma unroll
    for (int t = 0; t < 4; t++) {
        unsigned r = ranks[t];
        if (r >= pre && r < pre + local) {
            unsigned cum = pre;
            for (int j = 0; j < W; j++) {
                unsigned c = h[base + j];
                if (r < cum + c) {
                    g_tbin[b][t] = base + j;
                    g_trank[b][t] = (int)(r - cum);
                    break;
                }
                cum += c;
            }
        }
    }
}

// ------------- kernel 3: fine (4-bit) counts inside the 4 target coarse bins -------------
__global__ void __launch_bounds__(NT) k_fine() {
    __shared__ unsigned sf[64];
    __shared__ int stb[4];
    const int b = blockIdx.y;

    if (threadIdx.x < 64) sf[threadIdx.x] = 0u;
    if (threadIdx.x < 4) stb[threadIdx.x] = g_tbin[b][threadIdx.x];
    __syncthreads();
    const int t0 = stb[0], t1 = stb[1], t2 = stb[2], t3 = stb[3];

    const uint4* __restrict__ Y = (const uint4*)(g_Y16 + (size_t)b * HW);
    const int per_cta = (HW / 8) / CHUNKS;           // 2048 uint4
    const int off = blockIdx.x * per_cta;

    #pragma unroll 2
    for (int i = threadIdx.x; i < per_cta; i += NT) {
        uint4 x = Y[off + i];
        unsigned w[4] = {x.x, x.y, x.z, x.w};
        #pragma unroll
        for (int k = 0; k < 4; k++) {
            unsigned vlo = w[k] & 0xffffu;
            unsigned vhi = w[k] >> 16;
            int clo = (int)(vlo >> FBITS);
            int chi = (int)(vhi >> FBITS);
            if (clo == t0) atomicAdd(&sf[ 0 + (vlo & 15u)], 1u);
            if (clo == t1) atomicAdd(&sf[16 + (vlo & 15u)], 1u);
            if (clo == t2) atomicAdd(&sf[32 + (vlo & 15u)], 1u);
            if (clo == t3) atomicAdd(&sf[48 + (vlo & 15u)], 1u);
            if (chi == t0) atomicAdd(&sf[ 0 + (vhi & 15u)], 1u);
            if (chi == t1) atomicAdd(&sf[16 + (vhi & 15u)], 1u);
            if (chi == t2) atomicAdd(&sf[32 + (vhi & 15u)], 1u);
            if (chi == t3) atomicAdd(&sf[48 + (vhi & 15u)], 1u);
        }
    }
    __syncthreads();
    if (threadIdx.x < 64) {
        unsigned v = sf[threadIdx.x];
        if (v) atomicAdd(&((unsigned*)g_hist2[b])[threadIdx.x], v);
    }
}

// ------------- kernel 4: per-CTA redundant select, then apply. Zeroes g_hist. -------------
__global__ void __launch_bounds__(NT) k_apply(const float* __restrict__ img,
                                              float* __restrict__ out) {
    __shared__ float s_vals[4];
    __shared__ float s_bm[2];
    const int b = blockIdx.y;
    const int tid = threadIdx.x;

    // zero coarse hist for the next replay (fine+coarse_select already consumed it)
    {
        int cta = blockIdx.y * gridDim.x + blockIdx.x;
        if (cta < 256) ((unsigned*)g_hist)[cta * 256 + tid] = 0u;
    }

    // redundant select: threads 0..63 = (target t = tid>>4, fine bin j = tid&15)
    if (tid < 64) {
        const int t = tid >> 4;
        const int j = tid & 15;
        unsigned c = g_hist2[b][t][j];
        unsigned p = c;
        #pragma unroll
        for (int d = 1; d < 16; d <<= 1) {
            unsigned o = __shfl_up_sync(0xffffffffu, p, d, 16);
            if ((tid & 15) >= d) p += o;
        }
        unsigned pre = p - c;
        unsigned tr = (unsigned)g_trank[b][t];
        if (tr >= pre && tr < pre + c) {
            unsigned q = ((unsigned)g_tbin[b][t] << FBITS) | (unsigned)j;
            s_vals[t] = ((float)q + 0.5f) * (1.0f / 65536.0f);
        }
    }
    __syncthreads();
    if (tid == 0) {
        float blk = 0.25f * s_vals[0] + 0.75f * s_vals[1];
        float wht = 0.75f * s_vals[2] + 0.25f * s_vals[3];
        s_bm[0] = blk;
        s_bm[1] = fminf(1.0f / (wht - blk), 1.5f);
    }
    __syncthreads();
    const float blk = s_bm[0];
    const float m = s_bm[1];

    const size_t base = (size_t)b * 3 * (HW / 4);
    const float4* __restrict__ in4 = (const float4*)img + base;
    float4* __restrict__ o4 = (float4*)out + base;
    const int n = 3 * (HW / 4);
    const int stride = gridDim.x * NT;

    for (int i = blockIdx.x * NT + tid; i < n; i += stride) {
        float4 v = in4[i];
        float4 r;
        r.x = fminf(fmaxf((v.x - blk) * m, 0.0f), 1.0f);
        r.y = fminf(fmaxf((v.y - blk) * m, 0.0f), 1.0f);
        r.z = fminf(fmaxf((v.z - blk) * m, 0.0f), 1.0f);
        r.w = fminf(fmaxf((v.w - blk) * m, 0.0f), 1.0f);
        o4[i] = r;
    }
}

// ---------------- launch ----------------
extern "C" void kernel_launch(void* const* d_in, const int* in_sizes, int n_in,
                              void* d_out, int out_size) {
    const float* img = (const float*)d_in[0];
    const float* mat = (const float*)d_in[1];
    float* out = (float*)d_out;

    dim3 gBig(CHUNKS, BATCH);
    k_yhist<<<gBig, NT>>>(img, mat);
    k_coarse_select<<<BATCH, NT>>>();
    k_fine<<<gBig, NT>>>();
    dim3 gApply(384, BATCH);
    k_apply<<<gApply, NT>>>(img, out);
}